// round 14
// baseline (speedup 1.0000x reference)
#include <cuda_runtime.h>
#include <cuda_bf16.h>
#include <cstdint>

#define BB   16
#define TT   128
#define EE   512
#define HH   512
#define G4   2048      // 4*H
#define NLY  4
#define VT   32000
#define NTOK (BB*TT)   // 2048
#define NBLK 128       // recurrent grid: 2 groups x 64 blocks

// ---------------- scratch (device globals; no allocs allowed) ----------------
__device__ float g_xW[NTOK*G4];
__device__ float g_hbuf[2][BB*HH];
__device__ float g_hN[NLY*BB*HH];
__device__ float g_cN[NLY*BB*HH];
__device__ unsigned g_flags[NBLK * 32];     // per-block flag, each on own 128B line
// bf16 split buffers (activations ping-pong pairs A and B)
__device__ __nv_bfloat16 g_ahi[NTOK*EE], g_alo[NTOK*EE];
__device__ __nv_bfloat16 g_bhi[NTOK*EE], g_blo[NTOK*EE];
__device__ __nv_bfloat16 g_whi[G4*EE],  g_wlo[G4*EE];
__device__ __nv_bfloat16 g_fwhi[VT*EE], g_fwlo[VT*EE];

// ---------------- fp32 -> bf16 hi/lo split (weights only now) ----------------
__global__ void split_kernel(const float* __restrict__ in,
                             __nv_bfloat16* __restrict__ hi,
                             __nv_bfloat16* __restrict__ lo, int n4) {
    int i = blockIdx.x * blockDim.x + threadIdx.x;
    if (i >= n4) return;
    float4 v = ((const float4*)in)[i];
    __nv_bfloat16 h[4], l[4];
    float f[4] = { v.x, v.y, v.z, v.w };
#pragma unroll
    for (int j = 0; j < 4; j++) {
        h[j] = __float2bfloat16(f[j]);
        l[j] = __float2bfloat16(f[j] - __bfloat162float(h[j]));
    }
    ((uint2*)hi)[i] = *(uint2*)h;
    ((uint2*)lo)[i] = *(uint2*)l;
}

// ---------------- mma.sync / ldmatrix helpers ----------------
__device__ __forceinline__ void mma16816(float* d, const uint32_t* a, const uint32_t* b) {
    asm volatile(
        "mma.sync.aligned.m16n8k16.row.col.f32.bf16.bf16.f32 "
        "{%0,%1,%2,%3}, {%4,%5,%6,%7}, {%8,%9}, {%0,%1,%2,%3};"
        : "+f"(d[0]), "+f"(d[1]), "+f"(d[2]), "+f"(d[3])
        : "r"(a[0]), "r"(a[1]), "r"(a[2]), "r"(a[3]), "r"(b[0]), "r"(b[1]));
}
__device__ __forceinline__ void ldsm_x4(uint32_t* r, uint32_t addr) {
    asm volatile("ldmatrix.sync.aligned.m8n8.x4.shared.b16 {%0,%1,%2,%3}, [%4];"
        : "=r"(r[0]), "=r"(r[1]), "=r"(r[2]), "=r"(r[3]) : "r"(addr));
}
__device__ __forceinline__ uint32_t smem_u32(const void* p) {
    uint32_t a;
    asm("{ .reg .u64 t; cvta.to.shared.u64 t, %1; cvt.u32.u64 %0, t; }" : "=r"(a) : "l"(p));
    return a;
}
__device__ __forceinline__ void cp16(uint32_t dst, const void* src) {
    asm volatile("cp.async.cg.shared.global [%0], [%1], 16;" :: "r"(dst), "l"(src));
}

// ---------------- bf16 split GEMM: mma.sync + cp.async + ldmatrix (R13) ----------------
#define SMW 36
#define TILE_WORDS (128 * SMW)
#define BUF_WORDS  (4 * TILE_WORDS)
#define GEMM_SMEM  (2 * BUF_WORDS * 4)
__global__ __launch_bounds__(256)
void gemm_mma(const __nv_bfloat16* __restrict__ Ahi, const __nv_bfloat16* __restrict__ Alo,
              const __nv_bfloat16* __restrict__ Bhi, const __nv_bfloat16* __restrict__ Blo,
              const float* __restrict__ bias, float* __restrict__ C, int N) {
    extern __shared__ uint32_t sm[];
    const uint32_t sbase = smem_u32(sm);

    const int tid  = threadIdx.x;
    const int lane = tid & 31;
    const int wid  = tid >> 5;
    const int n0 = blockIdx.x * 128, m0 = blockIdx.y * 128;
    const int m0w = (wid & 1) * 64;
    const int n0w = (wid >> 1) * 32;
    const int lr = lane >> 2;
    const int lc = lane & 3;

    const int ra = (lane & 7) + ((lane >> 3) & 1) * 8;
    const int wa = (lane >> 4) * 4;
    const int rb = (lane & 7) + (lane >> 4) * 8;
    const int wb = ((lane >> 3) & 1) * 4;

    const __nv_bfloat16* bases[4] = {
        Ahi + (size_t)m0 * 512, Alo + (size_t)m0 * 512,
        Bhi + (size_t)n0 * 512, Blo + (size_t)n0 * 512 };

    const int lrow[4] = { (tid + 0) >> 3, (tid + 256) >> 3, (tid + 512) >> 3, (tid + 768) >> 3 };
    const int lg = tid & 7;

    auto load_buf = [&](int buf, int kc) {
        const int k0 = kc * 64;
        const uint32_t d0 = sbase + (uint32_t)buf * BUF_WORDS * 4;
#pragma unroll
        for (int tl = 0; tl < 4; tl++) {
            const __nv_bfloat16* s = bases[tl] + k0;
            const uint32_t dt = d0 + (uint32_t)tl * TILE_WORDS * 4;
#pragma unroll
            for (int i = 0; i < 4; i++) {
                int row = lrow[i];
                cp16(dt + (uint32_t)(row * SMW + lg * 4) * 4,
                     s + (size_t)row * 512 + lg * 8);
            }
        }
        asm volatile("cp.async.commit_group;" ::: "memory");
    };

    float acc[4][4][4];
#pragma unroll
    for (int i = 0; i < 4; i++)
#pragma unroll
        for (int j = 0; j < 4; j++)
#pragma unroll
            for (int q = 0; q < 4; q++) acc[i][j][q] = 0.f;

    load_buf(0, 0);

    for (int kc = 0; kc < 8; kc++) {
        if (kc + 1 < 8) {
            load_buf((kc + 1) & 1, kc + 1);
            asm volatile("cp.async.wait_group 1;" ::: "memory");
        } else {
            asm volatile("cp.async.wait_group 0;" ::: "memory");
        }
        __syncthreads();

        const uint32_t uAhi = sbase + (uint32_t)(kc & 1) * BUF_WORDS * 4;
        const uint32_t uAlo = uAhi + TILE_WORDS * 4;
        const uint32_t uBhi = uAhi + 2 * TILE_WORDS * 4;
        const uint32_t uBlo = uAhi + 3 * TILE_WORDS * 4;

#pragma unroll
        for (int kk = 0; kk < 4; kk++) {
            uint32_t ah[4][4], al[4][4], bh[4][2], bl[4][2];
#pragma unroll
            for (int mt = 0; mt < 4; mt++) {
                uint32_t off = (uint32_t)((m0w + mt * 16 + ra) * SMW + kk * 8 + wa) * 4;
                ldsm_x4(ah[mt], uAhi + off);
                ldsm_x4(al[mt], uAlo + off);
            }
#pragma unroll
            for (int p = 0; p < 2; p++) {
                uint32_t off = (uint32_t)((n0w + p * 16 + rb) * SMW + kk * 8 + wb) * 4;
                uint32_t rh[4], rl[4];
                ldsm_x4(rh, uBhi + off);
                ldsm_x4(rl, uBlo + off);
                bh[p*2][0] = rh[0]; bh[p*2][1] = rh[1];
                bh[p*2+1][0] = rh[2]; bh[p*2+1][1] = rh[3];
                bl[p*2][0] = rl[0]; bl[p*2][1] = rl[1];
                bl[p*2+1][0] = rl[2]; bl[p*2+1][1] = rl[3];
            }
#pragma unroll
            for (int mt = 0; mt < 4; mt++)
#pragma unroll
                for (int nt = 0; nt < 4; nt++) {
                    mma16816(acc[mt][nt], ah[mt], bh[nt]);
                    mma16816(acc[mt][nt], ah[mt], bl[nt]);
                    mma16816(acc[mt][nt], al[mt], bh[nt]);
                }
        }
        __syncthreads();
    }

#pragma unroll
    for (int nt = 0; nt < 4; nt++) {
        int col = n0 + n0w + nt * 8 + lc * 2;
        float2 bv = *(const float2*)&bias[col];
#pragma unroll
        for (int mt = 0; mt < 4; mt++) {
            int r = m0 + m0w + mt * 16 + lr;
            *(float2*)&C[(size_t)r * N + col] =
                make_float2(acc[mt][nt][0] + bv.x, acc[mt][nt][1] + bv.y);
            *(float2*)&C[(size_t)(r + 8) * N + col] =
                make_float2(acc[mt][nt][2] + bv.x, acc[mt][nt][3] + bv.y);
        }
    }
}

// ---------------- embedding gather, writes hi/lo bf16 directly ----------------
__global__ void embed_kernel(const int* __restrict__ idx,
                             const float* __restrict__ emb,
                             __nv_bfloat16* __restrict__ hi,
                             __nv_bfloat16* __restrict__ lo) {
    int row = blockIdx.x;
    int v   = idx[row];
    float4 f = ((const float4*)(emb + (size_t)v * EE))[threadIdx.x];
    float fv[4] = { f.x, f.y, f.z, f.w };
    __nv_bfloat16 h[4], l[4];
#pragma unroll
    for (int j = 0; j < 4; j++) {
        h[j] = __float2bfloat16(fv[j]);
        l[j] = __float2bfloat16(fv[j] - __bfloat162float(h[j]));
    }
    ((uint2*)(hi + (size_t)row * EE))[threadIdx.x] = *(uint2*)h;
    ((uint2*)(lo + (size_t)row * EE))[threadIdx.x] = *(uint2*)l;
}

// ---------------- packed f32x2 helpers ----------------
__device__ __forceinline__ void fma2(unsigned long long &acc,
                                     unsigned long long a, unsigned long long b) {
    asm("fma.rn.f32x2 %0, %1, %2, %0;" : "+l"(acc) : "l"(a), "l"(b));
}
__device__ __forceinline__ float lo32(unsigned long long v) { return __uint_as_float((unsigned)v); }
__device__ __forceinline__ float hi32(unsigned long long v) { return __uint_as_float((unsigned)(v >> 32)); }

__device__ __forceinline__ float sigmoidf_(float x) { return 1.0f / (1.0f + expf(-x)); }

// ---------------- persistent LSTM layer ----------------
// 2 groups x 64 blocks x 256 threads. Per step:
//  - each warp self-loads its own h segment (syncwarp, not syncthreads)
//  - GEMV -> red; __syncthreads
//  - warps 0-1: fused pointwise + h/x(hi,lo) stores + bar64 + flag store
//  - warp 2: polls the 64 group flags CONCURRENTLY with pointwise
//  - __syncthreads releases the block into step t+1
__global__ __launch_bounds__(256)
void lstm_layer(const float* __restrict__ xW, const float* __restrict__ Whh,
                __nv_bfloat16* __restrict__ xhi, __nv_bfloat16* __restrict__ xlo,
                const float* __restrict__ h0, const float* __restrict__ c0,
                float* __restrict__ hN, float* __restrict__ cN) {
    __shared__ float h_s[8 * HH];           // 16KB
    __shared__ float red[8 * 8 * 33];       // [b][seg][row pad33]
    __shared__ float c_s[8][8];             // [kx][b]
    __shared__ unsigned s_base;

    const int tid = threadIdx.x;
    const int bk  = blockIdx.x;
    const int grp = bk >> 6;
    const int lbk = bk & 63;
    const int k0  = lbk * 8;
    const int jj  = tid & 31;
    const int seg = tid >> 5;
    const int gate = jj >> 3;
    const int jrow = gate * 512 + k0 + (jj & 7);
    const int b0flag = grp * 64;

    if (tid == 0) s_base = *(volatile unsigned*)&g_flags[bk * 32];

    unsigned long long w2[32];
    {
        const float* wr = Whh + (size_t)jrow * 512 + seg * 64;
#pragma unroll
        for (int u = 0; u < 32; u++)
            w2[u] = *reinterpret_cast<const unsigned long long*>(wr + u * 2);
    }

    // pointwise-thread mapping (tid < 64)
    const int pb = tid & 7, pkx = tid >> 3;
    const size_t xw_pbase = ((size_t)(grp * 8 + pb) * TT) * G4 + k0 + pkx;

    // warp-self h load coords: 4 float4 per lane
    int hb[4], hf[4];
#pragma unroll
    for (int u = 0; u < 4; u++) {
        int idx = jj + u * 32;               // 0..127
        hb[u] = idx >> 4;
        hf[u] = hb[u] * 128 + seg * 16 + (idx & 15);
    }

    float h_last = 0.f, c_last = 0.f;
    if (tid < 64) {
        int gbat = grp * 8 + pb, k = k0 + pkx;
        c_s[pkx][pb] = c0 ? c0[gbat * HH + k] : 0.f;
        g_hbuf[0][gbat * HH + k] = h0 ? h0[gbat * HH + k] : 0.f;
    }
    __syncthreads();
    unsigned base = s_base;
    unsigned target = base + 1;

    // initial publish of h/c (poll by warp 2)
    if (tid == 0) {
        __threadfence();
        *(volatile unsigned*)&g_flags[bk * 32] = target;
    }
    if (tid >= 64 && tid < 96) {
        int ln = tid - 64;
        for (;;) {
            unsigned v0 = *(volatile unsigned*)&g_flags[(b0flag + ln) * 32];
            unsigned v1 = *(volatile unsigned*)&g_flags[(b0flag + 32 + ln) * 32];
            bool ok = ((int)(v0 - target) >= 0) && ((int)(v1 - target) >= 0);
            if (__all_sync(0xffffffffu, ok)) break;
        }
    }
    __syncthreads();

    for (int t = 0; t < TT; t++) {
        // prefetch this step's 4 gate xW values (pointwise threads only)
        float xg[4];
        if (tid < 64) {
            const float* xp = xW + xw_pbase + (size_t)t * G4;
#pragma unroll
            for (int g = 0; g < 4; g++) xg[g] = __ldg(xp + g * 512);
        }

        // warp-self h staging (only own-warp data -> syncwarp suffices)
        {
            const float4* gh4 = (const float4*)g_hbuf[t & 1] + grp * 1024;
            float4* hs4 = (float4*)h_s;
#pragma unroll
            for (int u = 0; u < 4; u++)
                hs4[hf[u]] = __ldcg(gh4 + hf[u]);
            __syncwarp();
        }

        unsigned long long acc[8];
#pragma unroll
        for (int b = 0; b < 8; b++) acc[b] = 0ull;
#pragma unroll
        for (int u = 0; u < 32; u += 2) {
            const unsigned long long wa = w2[u], wb = w2[u + 1];
#pragma unroll
            for (int b = 0; b < 8; b++) {
                ulonglong2 hv = *reinterpret_cast<const ulonglong2*>(
                    &h_s[b * HH + seg * 64 + u * 2]);
                fma2(acc[b], wa, hv.x);
                fma2(acc[b], wb, hv.y);
            }
        }
#pragma unroll
        for (int b = 0; b < 8; b++)
            red[(b * 8 + seg) * 33 + jj] = lo32(acc[b]) + hi32(acc[b]);
        __syncthreads();

        if (tid < 64) {
            // fused gather + pointwise (warps 0-1)
            float gv[4];
#pragma unroll
            for (int g = 0; g < 4; g++) {
                float p = xg[g];
#pragma unroll
                for (int s = 0; s < 8; s++)
                    p += red[(pb * 8 + s) * 33 + g * 8 + pkx];
                gv[g] = p;
            }
            int gbat = grp * 8 + pb, k = k0 + pkx;
            float cold = c_s[pkx][pb];
            float cn = sigmoidf_(gv[1]) * cold + sigmoidf_(gv[0]) * tanhf(gv[2]);
            float hn = sigmoidf_(gv[3]) * tanhf(cn);
            c_s[pkx][pb] = cn;
            h_last = hn; c_last = cn;
            g_hbuf[(t + 1) & 1][gbat * HH + k] = hn;
            __nv_bfloat16 hh = __float2bfloat16(hn);
            __nv_bfloat16 hl = __float2bfloat16(hn - __bfloat162float(hh));
            size_t xo = ((size_t)gbat * TT + t) * HH + k;
            xhi[xo] = hh;
            xlo[xo] = hl;
            asm volatile("bar.sync 1, 64;" ::: "memory");
            if (tid == 0) {
                __threadfence();
                *(volatile unsigned*)&g_flags[bk * 32] = target + 1;
            }
        } else if (tid < 96) {
            // dedicated poll warp: overlaps pointwise
            int ln = tid - 64;
            unsigned tg = target + 1;
            for (;;) {
                unsigned v0 = *(volatile unsigned*)&g_flags[(b0flag + ln) * 32];
                unsigned v1 = *(volatile unsigned*)&g_flags[(b0flag + 32 + ln) * 32];
                bool ok = ((int)(v0 - tg) >= 0) && ((int)(v1 - tg) >= 0);
                if (__all_sync(0xffffffffu, ok)) break;
            }
        }
        ++target;
        __syncthreads();
    }

    if (hN != nullptr && tid < 64) {
        int gbat = grp * 8 + pb, k = k0 + pkx;
        hN[gbat * HH + k] = h_last;
        cN[gbat * HH + k] = c_last;
    }
}

// ---------------- host orchestration ----------------
extern "C" void kernel_launch(void* const* d_in, const int* in_sizes, int n_in,
                              void* d_out, int out_size) {
    (void)in_sizes; (void)n_in; (void)out_size;
    const int*   src     = (const int*)  d_in[0];
    const int*   tgt     = (const int*)  d_in[1];
    const float* src_emb = (const float*)d_in[2];
    const float* tgt_emb = (const float*)d_in[3];
    const float* enc_Wih = (const float*)d_in[4];
    const float* enc_Whh = (const float*)d_in[5];
    const float* enc_b   = (const float*)d_in[6];
    const float* dec_Wih = (const float*)d_in[7];
    const float* dec_Whh = (const float*)d_in[8];
    const float* dec_b   = (const float*)d_in[9];
    const float* fc_W    = (const float*)d_in[10];
    const float* fc_b    = (const float*)d_in[11];
    float* out = (float*)d_out;

    float *xw, *hN, *cN;
    __nv_bfloat16 *ahi, *alo, *bhi, *blo, *whi, *wlo, *fwhi, *fwlo;
    cudaGetSymbolAddress((void**)&xw, g_xW);
    cudaGetSymbolAddress((void**)&hN, g_hN);
    cudaGetSymbolAddress((void**)&cN, g_cN);
    cudaGetSymbolAddress((void**)&ahi, g_ahi);
    cudaGetSymbolAddress((void**)&alo, g_alo);
    cudaGetSymbolAddress((void**)&bhi, g_bhi);
    cudaGetSymbolAddress((void**)&blo, g_blo);
    cudaGetSymbolAddress((void**)&whi, g_whi);
    cudaGetSymbolAddress((void**)&wlo, g_wlo);
    cudaGetSymbolAddress((void**)&fwhi, g_fwhi);
    cudaGetSymbolAddress((void**)&fwlo, g_fwlo);

    cudaFuncSetAttribute(gemm_mma, cudaFuncAttributeMaxDynamicSharedMemorySize, GEMM_SMEM);

    const int WN4 = G4 * EE / 4;
    const int FN4 = VT * EE / 4;

    split_kernel<<<(FN4 + 255) / 256, 256>>>(fc_W, fwhi, fwlo, FN4);

    // activation ping-pong: layer l reads pair (l even ? A : B), writes the other
    __nv_bfloat16* phi[2] = { ahi, bhi };
    __nv_bfloat16* plo[2] = { alo, blo };

    // ---- encoder ----
    embed_kernel<<<NTOK, 128>>>(src, src_emb, ahi, alo);
    for (int l = 0; l < NLY; l++) {
        int ri = l & 1, wi = ri ^ 1;
        split_kernel<<<(WN4 + 255) / 256, 256>>>(enc_Wih + (size_t)l * G4 * EE, whi, wlo, WN4);
        gemm_mma<<<dim3(G4 / 128, NTOK / 128), 256, GEMM_SMEM>>>(
            phi[ri], plo[ri], whi, wlo, enc_b + l * G4, xw, G4);
        lstm_layer<<<NBLK, 256>>>(xw, enc_Whh + (size_t)l * G4 * HH,
                                  phi[wi], plo[wi], nullptr, nullptr,
                                  hN + l * BB * HH, cN + l * BB * HH);
    }
    // ---- decoder ----
    embed_kernel<<<NTOK, 128>>>(tgt, tgt_emb, ahi, alo);
    for (int l = 0; l < NLY; l++) {
        int ri = l & 1, wi = ri ^ 1;
        split_kernel<<<(WN4 + 255) / 256, 256>>>(dec_Wih + (size_t)l * G4 * EE, whi, wlo, WN4);
        gemm_mma<<<dim3(G4 / 128, NTOK / 128), 256, GEMM_SMEM>>>(
            phi[ri], plo[ri], whi, wlo, dec_b + l * G4, xw, G4);
        lstm_layer<<<NBLK, 256>>>(xw, dec_Whh + (size_t)l * G4 * HH,
                                  phi[wi], plo[wi],
                                  hN + l * BB * HH, cN + l * BB * HH,
                                  nullptr, nullptr);
    }
    // ---- vocab projection (decoder l=3 wrote pair A) ----
    gemm_mma<<<dim3(VT / 128, NTOK / 128), 256, GEMM_SMEM>>>(
        ahi, alo, fwhi, fwlo, fc_b, out, VT);
}

// round 15
// speedup vs baseline: 1.0161x; 1.0161x over previous
#include <cuda_runtime.h>
#include <cuda_bf16.h>
#include <cstdint>

#define BB   16
#define TT   128
#define EE   512
#define HH   512
#define G4   2048      // 4*H
#define NLY  4
#define VT   32000
#define NTOK (BB*TT)   // 2048
#define NBLK 128       // recurrent grid: 2 groups x 64 blocks

// ---------------- scratch (device globals; no allocs allowed) ----------------
__device__ float g_xW[NTOK*G4];
__device__ float g_hbuf[2][BB*HH];
__device__ float g_hN[NLY*BB*HH];
__device__ float g_cN[NLY*BB*HH];
__device__ unsigned g_flags[NBLK * 32];     // per-block flag, each on own 128B line
// bf16 split buffers (activations ping-pong pairs A and B)
__device__ __nv_bfloat16 g_ahi[NTOK*EE], g_alo[NTOK*EE];
__device__ __nv_bfloat16 g_bhi[NTOK*EE], g_blo[NTOK*EE];
__device__ __nv_bfloat16 g_whi[G4*EE],  g_wlo[G4*EE];
__device__ __nv_bfloat16 g_fwhi[VT*EE], g_fwlo[VT*EE];

// ---------------- fp32 -> bf16 hi/lo split (weights only) ----------------
__global__ void split_kernel(const float* __restrict__ in,
                             __nv_bfloat16* __restrict__ hi,
                             __nv_bfloat16* __restrict__ lo, int n4) {
    int i = blockIdx.x * blockDim.x + threadIdx.x;
    if (i >= n4) return;
    float4 v = ((const float4*)in)[i];
    __nv_bfloat16 h[4], l[4];
    float f[4] = { v.x, v.y, v.z, v.w };
#pragma unroll
    for (int j = 0; j < 4; j++) {
        h[j] = __float2bfloat16(f[j]);
        l[j] = __float2bfloat16(f[j] - __bfloat162float(h[j]));
    }
    ((uint2*)hi)[i] = *(uint2*)h;
    ((uint2*)lo)[i] = *(uint2*)l;
}

// ---------------- mma.sync / ldmatrix helpers ----------------
__device__ __forceinline__ void mma16816(float* d, const uint32_t* a, const uint32_t* b) {
    asm volatile(
        "mma.sync.aligned.m16n8k16.row.col.f32.bf16.bf16.f32 "
        "{%0,%1,%2,%3}, {%4,%5,%6,%7}, {%8,%9}, {%0,%1,%2,%3};"
        : "+f"(d[0]), "+f"(d[1]), "+f"(d[2]), "+f"(d[3])
        : "r"(a[0]), "r"(a[1]), "r"(a[2]), "r"(a[3]), "r"(b[0]), "r"(b[1]));
}
__device__ __forceinline__ void ldsm_x4(uint32_t* r, uint32_t addr) {
    asm volatile("ldmatrix.sync.aligned.m8n8.x4.shared.b16 {%0,%1,%2,%3}, [%4];"
        : "=r"(r[0]), "=r"(r[1]), "=r"(r[2]), "=r"(r[3]) : "r"(addr));
}
__device__ __forceinline__ uint32_t smem_u32(const void* p) {
    uint32_t a;
    asm("{ .reg .u64 t; cvta.to.shared.u64 t, %1; cvt.u32.u64 %0, t; }" : "=r"(a) : "l"(p));
    return a;
}
__device__ __forceinline__ void cp16(uint32_t dst, const void* src) {
    asm volatile("cp.async.cg.shared.global [%0], [%1], 16;" :: "r"(dst), "l"(src));
}

// ---------------- bf16 split GEMM: mma.sync + 3-stage cp.async + ldmatrix ----------------
#define SMW 36
#define TILE_WORDS (128 * SMW)
#define BUF_WORDS  (4 * TILE_WORDS)
#define GEMM_SMEM  (3 * BUF_WORDS * 4)      // 221184 bytes (3-stage)
__global__ __launch_bounds__(256)
void gemm_mma(const __nv_bfloat16* __restrict__ Ahi, const __nv_bfloat16* __restrict__ Alo,
              const __nv_bfloat16* __restrict__ Bhi, const __nv_bfloat16* __restrict__ Blo,
              const float* __restrict__ bias, float* __restrict__ C, int N) {
    extern __shared__ uint32_t sm[];
    const uint32_t sbase = smem_u32(sm);

    const int tid  = threadIdx.x;
    const int lane = tid & 31;
    const int wid  = tid >> 5;
    const int n0 = blockIdx.x * 128, m0 = blockIdx.y * 128;
    const int m0w = (wid & 1) * 64;
    const int n0w = (wid >> 1) * 32;
    const int lr = lane >> 2;
    const int lc = lane & 3;

    const int ra = (lane & 7) + ((lane >> 3) & 1) * 8;
    const int wa = (lane >> 4) * 4;
    const int rb = (lane & 7) + (lane >> 4) * 8;
    const int wb = ((lane >> 3) & 1) * 4;

    const __nv_bfloat16* bases[4] = {
        Ahi + (size_t)m0 * 512, Alo + (size_t)m0 * 512,
        Bhi + (size_t)n0 * 512, Blo + (size_t)n0 * 512 };

    const int lrow[4] = { (tid + 0) >> 3, (tid + 256) >> 3, (tid + 512) >> 3, (tid + 768) >> 3 };
    const int lg = tid & 7;

    auto load_buf = [&](int buf, int kc) {
        const int k0 = kc * 64;
        const uint32_t d0 = sbase + (uint32_t)buf * BUF_WORDS * 4;
#pragma unroll
        for (int tl = 0; tl < 4; tl++) {
            const __nv_bfloat16* s = bases[tl] + k0;
            const uint32_t dt = d0 + (uint32_t)tl * TILE_WORDS * 4;
#pragma unroll
            for (int i = 0; i < 4; i++) {
                int row = lrow[i];
                cp16(dt + (uint32_t)(row * SMW + lg * 4) * 4,
                     s + (size_t)row * 512 + lg * 8);
            }
        }
        asm volatile("cp.async.commit_group;" ::: "memory");
    };

    float acc[4][4][4];
#pragma unroll
    for (int i = 0; i < 4; i++)
#pragma unroll
        for (int j = 0; j < 4; j++)
#pragma unroll
            for (int q = 0; q < 4; q++) acc[i][j][q] = 0.f;

    load_buf(0, 0);
    load_buf(1, 1);

    int buf = 0;
    for (int kc = 0; kc < 8; kc++) {
        if (kc < 7) {
            asm volatile("cp.async.wait_group 1;" ::: "memory");
        } else {
            asm volatile("cp.async.wait_group 0;" ::: "memory");
        }
        __syncthreads();

        const uint32_t uAhi = sbase + (uint32_t)buf * BUF_WORDS * 4;
        const uint32_t uAlo = uAhi + TILE_WORDS * 4;
        const uint32_t uBhi = uAhi + 2 * TILE_WORDS * 4;
        const uint32_t uBlo = uAhi + 3 * TILE_WORDS * 4;

#pragma unroll
        for (int kk = 0; kk < 4; kk++) {
            uint32_t ah[4][4], al[4][4], bh[4][2], bl[4][2];
#pragma unroll
            for (int mt = 0; mt < 4; mt++) {
                uint32_t off = (uint32_t)((m0w + mt * 16 + ra) * SMW + kk * 8 + wa) * 4;
                ldsm_x4(ah[mt], uAhi + off);
                ldsm_x4(al[mt], uAlo + off);
            }
#pragma unroll
            for (int p = 0; p < 2; p++) {
                uint32_t off = (uint32_t)((n0w + p * 16 + rb) * SMW + kk * 8 + wb) * 4;
                uint32_t rh[4], rl[4];
                ldsm_x4(rh, uBhi + off);
                ldsm_x4(rl, uBlo + off);
                bh[p*2][0] = rh[0]; bh[p*2][1] = rh[1];
                bh[p*2+1][0] = rh[2]; bh[p*2+1][1] = rh[3];
                bl[p*2][0] = rl[0]; bl[p*2][1] = rl[1];
                bl[p*2+1][0] = rl[2]; bl[p*2+1][1] = rl[3];
            }
#pragma unroll
            for (int mt = 0; mt < 4; mt++)
#pragma unroll
                for (int nt = 0; nt < 4; nt++) {
                    mma16816(acc[mt][nt], ah[mt], bh[nt]);
                    mma16816(acc[mt][nt], ah[mt], bl[nt]);
                    mma16816(acc[mt][nt], al[mt], bh[nt]);
                }
        }
        if (kc + 2 < 8) {
            int nb = buf + 2; if (nb >= 3) nb -= 3;
            load_buf(nb, kc + 2);
        }
        if (++buf == 3) buf = 0;
    }

#pragma unroll
    for (int nt = 0; nt < 4; nt++) {
        int col = n0 + n0w + nt * 8 + lc * 2;
        float2 bv = *(const float2*)&bias[col];
#pragma unroll
        for (int mt = 0; mt < 4; mt++) {
            int r = m0 + m0w + mt * 16 + lr;
            *(float2*)&C[(size_t)r * N + col] =
                make_float2(acc[mt][nt][0] + bv.x, acc[mt][nt][1] + bv.y);
            *(float2*)&C[(size_t)(r + 8) * N + col] =
                make_float2(acc[mt][nt][2] + bv.x, acc[mt][nt][3] + bv.y);
        }
    }
}

// ---------------- embedding gather, writes hi/lo bf16 directly ----------------
__global__ void embed_kernel(const int* __restrict__ idx,
                             const float* __restrict__ emb,
                             __nv_bfloat16* __restrict__ hi,
                             __nv_bfloat16* __restrict__ lo) {
    int row = blockIdx.x;
    int v   = idx[row];
    float4 f = ((const float4*)(emb + (size_t)v * EE))[threadIdx.x];
    float fv[4] = { f.x, f.y, f.z, f.w };
    __nv_bfloat16 h[4], l[4];
#pragma unroll
    for (int j = 0; j < 4; j++) {
        h[j] = __float2bfloat16(fv[j]);
        l[j] = __float2bfloat16(fv[j] - __bfloat162float(h[j]));
    }
    ((uint2*)(hi + (size_t)row * EE))[threadIdx.x] = *(uint2*)h;
    ((uint2*)(lo + (size_t)row * EE))[threadIdx.x] = *(uint2*)l;
}

// ---------------- packed f32x2 helpers ----------------
__device__ __forceinline__ void fma2(unsigned long long &acc,
                                     unsigned long long a, unsigned long long b) {
    asm("fma.rn.f32x2 %0, %1, %2, %0;" : "+l"(acc) : "l"(a), "l"(b));
}
__device__ __forceinline__ float lo32(unsigned long long v) { return __uint_as_float((unsigned)v); }
__device__ __forceinline__ float hi32(unsigned long long v) { return __uint_as_float((unsigned)(v >> 32)); }

__device__ __forceinline__ float sigmoidf_(float x) { return 1.0f / (1.0f + expf(-x)); }

// ---------------- persistent LSTM layer ----------------
// 2 groups x 64 blocks x 256 threads. R13 control flow (warp 0 polls after
// pointwise — NO continuous poll warp), plus warp-self h staging (syncwarp)
// and fused bf16 hi/lo x-output writes.
__global__ __launch_bounds__(256)
void lstm_layer(const float* __restrict__ xW, const float* __restrict__ Whh,
                __nv_bfloat16* __restrict__ xhi, __nv_bfloat16* __restrict__ xlo,
                const float* __restrict__ h0, const float* __restrict__ c0,
                float* __restrict__ hN, float* __restrict__ cN) {
    __shared__ float h_s[8 * HH];           // 16KB
    __shared__ float red[8 * 8 * 33];       // [b][seg][row pad33]
    __shared__ float c_s[8][8];             // [kx][b]
    __shared__ unsigned s_base;

    const int tid = threadIdx.x;
    const int bk  = blockIdx.x;
    const int grp = bk >> 6;
    const int lbk = bk & 63;
    const int k0  = lbk * 8;
    const int jj  = tid & 31;
    const int seg = tid >> 5;
    const int gate = jj >> 3;
    const int jrow = gate * 512 + k0 + (jj & 7);
    const int b0flag = grp * 64;

    if (tid == 0) s_base = *(volatile unsigned*)&g_flags[bk * 32];

    unsigned long long w2[32];
    {
        const float* wr = Whh + (size_t)jrow * 512 + seg * 64;
#pragma unroll
        for (int u = 0; u < 32; u++)
            w2[u] = *reinterpret_cast<const unsigned long long*>(wr + u * 2);
    }

    const int pb = tid & 7, pkx = tid >> 3;     // pointwise mapping (tid<64)
    const size_t xw_pbase = ((size_t)(grp * 8 + pb) * TT) * G4 + k0 + pkx;

    // warp-self h staging coords: warp seg loads [b][seg*64 .. +64) for b=0..7
    int hf[4];
#pragma unroll
    for (int u = 0; u < 4; u++) {
        int idx = jj + u * 32;                  // 0..127
        hf[u] = (idx >> 4) * 128 + seg * 16 + (idx & 15);
    }

    float h_last = 0.f, c_last = 0.f;
    if (tid < 64) {
        int gbat = grp * 8 + pb, k = k0 + pkx;
        c_s[pkx][pb] = c0 ? c0[gbat * HH + k] : 0.f;
        g_hbuf[0][gbat * HH + k] = h0 ? h0[gbat * HH + k] : 0.f;
    }
    __syncthreads();
    unsigned base = s_base;
    unsigned target = base + 1;

    // initial publish of h/c
    if (tid == 0) {
        __threadfence();
        *(volatile unsigned*)&g_flags[bk * 32] = target;
    }
    if (tid < 32) {
        for (;;) {
            unsigned v0 = *(volatile unsigned*)&g_flags[(b0flag + tid) * 32];
            unsigned v1 = *(volatile unsigned*)&g_flags[(b0flag + 32 + tid) * 32];
            bool ok = ((int)(v0 - target) >= 0) && ((int)(v1 - target) >= 0);
            if (__all_sync(0xffffffffu, ok)) break;
        }
    }
    __syncthreads();

    for (int t = 0; t < TT; t++) {
        // prefetch this step's 4 gate xW values (pointwise threads only)
        float xg[4];
        if (tid < 64) {
            const float* xp = xW + xw_pbase + (size_t)t * G4;
#pragma unroll
            for (int g = 0; g < 4; g++) xg[g] = __ldg(xp + g * 512);
        }

        // warp-self h staging (warp reads only what it wrote -> syncwarp)
        {
            const float4* gh4 = (const float4*)g_hbuf[t & 1] + grp * 1024;
            float4* hs4 = (float4*)h_s;
#pragma unroll
            for (int u = 0; u < 4; u++)
                hs4[hf[u]] = __ldcg(gh4 + hf[u]);
            __syncwarp();
        }

        unsigned long long acc[8];
#pragma unroll
        for (int b = 0; b < 8; b++) acc[b] = 0ull;
#pragma unroll
        for (int u = 0; u < 32; u += 2) {
            const unsigned long long wa = w2[u], wb = w2[u + 1];
#pragma unroll
            for (int b = 0; b < 8; b++) {
                ulonglong2 hv = *reinterpret_cast<const ulonglong2*>(
                    &h_s[b * HH + seg * 64 + u * 2]);
                fma2(acc[b], wa, hv.x);
                fma2(acc[b], wb, hv.y);
            }
        }
#pragma unroll
        for (int b = 0; b < 8; b++)
            red[(b * 8 + seg) * 33 + jj] = lo32(acc[b]) + hi32(acc[b]);
        __syncthreads();

        // fused gather + pointwise (warps 0-1)
        if (tid < 64) {
            float gv[4];
#pragma unroll
            for (int g = 0; g < 4; g++) {
                float p = xg[g];
#pragma unroll
                for (int s = 0; s < 8; s++)
                    p += red[(pb * 8 + s) * 33 + g * 8 + pkx];
                gv[g] = p;
            }
            int gbat = grp * 8 + pb, k = k0 + pkx;
            float cold = c_s[pkx][pb];
            float cn = sigmoidf_(gv[1]) * cold + sigmoidf_(gv[0]) * tanhf(gv[2]);
            float hn = sigmoidf_(gv[3]) * tanhf(cn);
            c_s[pkx][pb] = cn;
            h_last = hn; c_last = cn;
            g_hbuf[(t + 1) & 1][gbat * HH + k] = hn;
            __nv_bfloat16 hh = __float2bfloat16(hn);
            __nv_bfloat16 hl = __float2bfloat16(hn - __bfloat162float(hh));
            size_t xo = ((size_t)gbat * TT + t) * HH + k;
            xhi[xo] = hh;
            xlo[xo] = hl;
            asm volatile("bar.sync 1, 64;" ::: "memory");
            if (tid == 0) {
                __threadfence();
                *(volatile unsigned*)&g_flags[bk * 32] = target + 1;
            }
        }
        ++target;
        // warp 0 polls after pointwise (R13 placement — no continuous poll)
        if (tid < 32) {
            for (;;) {
                unsigned v0 = *(volatile unsigned*)&g_flags[(b0flag + tid) * 32];
                unsigned v1 = *(volatile unsigned*)&g_flags[(b0flag + 32 + tid) * 32];
                bool ok = ((int)(v0 - target) >= 0) && ((int)(v1 - target) >= 0);
                if (__all_sync(0xffffffffu, ok)) break;
            }
        }
        __syncthreads();
    }

    if (hN != nullptr && tid < 64) {
        int gbat = grp * 8 + pb, k = k0 + pkx;
        hN[gbat * HH + k] = h_last;
        cN[gbat * HH + k] = c_last;
    }
}

// ---------------- host orchestration ----------------
extern "C" void kernel_launch(void* const* d_in, const int* in_sizes, int n_in,
                              void* d_out, int out_size) {
    (void)in_sizes; (void)n_in; (void)out_size;
    const int*   src     = (const int*)  d_in[0];
    const int*   tgt     = (const int*)  d_in[1];
    const float* src_emb = (const float*)d_in[2];
    const float* tgt_emb = (const float*)d_in[3];
    const float* enc_Wih = (const float*)d_in[4];
    const float* enc_Whh = (const float*)d_in[5];
    const float* enc_b   = (const float*)d_in[6];
    const float* dec_Wih = (const float*)d_in[7];
    const float* dec_Whh = (const float*)d_in[8];
    const float* dec_b   = (const float*)d_in[9];
    const float* fc_W    = (const float*)d_in[10];
    const float* fc_b    = (const float*)d_in[11];
    float* out = (float*)d_out;

    float *xw, *hN, *cN;
    __nv_bfloat16 *ahi, *alo, *bhi, *blo, *whi, *wlo, *fwhi, *fwlo;
    cudaGetSymbolAddress((void**)&xw, g_xW);
    cudaGetSymbolAddress((void**)&hN, g_hN);
    cudaGetSymbolAddress((void**)&cN, g_cN);
    cudaGetSymbolAddress((void**)&ahi, g_ahi);
    cudaGetSymbolAddress((void**)&alo, g_alo);
    cudaGetSymbolAddress((void**)&bhi, g_bhi);
    cudaGetSymbolAddress((void**)&blo, g_blo);
    cudaGetSymbolAddress((void**)&whi, g_whi);
    cudaGetSymbolAddress((void**)&wlo, g_wlo);
    cudaGetSymbolAddress((void**)&fwhi, g_fwhi);
    cudaGetSymbolAddress((void**)&fwlo, g_fwlo);

    cudaFuncSetAttribute(gemm_mma, cudaFuncAttributeMaxDynamicSharedMemorySize, GEMM_SMEM);

    const int WN4 = G4 * EE / 4;
    const int FN4 = VT * EE / 4;

    split_kernel<<<(FN4 + 255) / 256, 256>>>(fc_W, fwhi, fwlo, FN4);

    __nv_bfloat16* phi[2] = { ahi, bhi };
    __nv_bfloat16* plo[2] = { alo, blo };

    // ---- encoder ----
    embed_kernel<<<NTOK, 128>>>(src, src_emb, ahi, alo);
    for (int l = 0; l < NLY; l++) {
        int ri = l & 1, wi = ri ^ 1;
        split_kernel<<<(WN4 + 255) / 256, 256>>>(enc_Wih + (size_t)l * G4 * EE, whi, wlo, WN4);
        gemm_mma<<<dim3(G4 / 128, NTOK / 128), 256, GEMM_SMEM>>>(
            phi[ri], plo[ri], whi, wlo, enc_b + l * G4, xw, G4);
        lstm_layer<<<NBLK, 256>>>(xw, enc_Whh + (size_t)l * G4 * HH,
                                  phi[wi], plo[wi], nullptr, nullptr,
                                  hN + l * BB * HH, cN + l * BB * HH);
    }
    // ---- decoder ----
    embed_kernel<<<NTOK, 128>>>(tgt, tgt_emb, ahi, alo);
    for (int l = 0; l < NLY; l++) {
        int ri = l & 1, wi = ri ^ 1;
        split_kernel<<<(WN4 + 255) / 256, 256>>>(dec_Wih + (size_t)l * G4 * EE, whi, wlo, WN4);
        gemm_mma<<<dim3(G4 / 128, NTOK / 128), 256, GEMM_SMEM>>>(
            phi[ri], plo[ri], whi, wlo, dec_b + l * G4, xw, G4);
        lstm_layer<<<NBLK, 256>>>(xw, dec_Whh + (size_t)l * G4 * HH,
                                  phi[wi], plo[wi],
                                  hN + l * BB * HH, cN + l * BB * HH,
                                  nullptr, nullptr);
    }
    // ---- vocab projection (decoder l=3 wrote pair A) ----
    gemm_mma<<<dim3(VT / 128, NTOK / 128), 256, GEMM_SMEM>>>(
        ahi, alo, fwhi, fwlo, fc_b, out, VT);
}

// round 16
// speedup vs baseline: 1.0601x; 1.0434x over previous
#include <cuda_runtime.h>
#include <cuda_bf16.h>
#include <cstdint>

#define BB   16
#define TT   128
#define EE   512
#define HH   512
#define G4   2048      // 4*H
#define NLY  4
#define VT   32000
#define NTOK (BB*TT)   // 2048
#define NBLK 128       // recurrent grid: 4 groups x 32 blocks

// ---------------- scratch (device globals; no allocs allowed) ----------------
__device__ float g_xW[NTOK*G4];
__device__ float g_hbuf[2][BB*HH];
__device__ float g_hN[NLY*BB*HH];
__device__ float g_cN[NLY*BB*HH];
__device__ unsigned g_flags[NBLK * 32];     // per-block flag, each on own 128B line
// bf16 split buffers (activations ping-pong pairs A and B)
__device__ __nv_bfloat16 g_ahi[NTOK*EE], g_alo[NTOK*EE];
__device__ __nv_bfloat16 g_bhi[NTOK*EE], g_blo[NTOK*EE];
__device__ __nv_bfloat16 g_whi[G4*EE],  g_wlo[G4*EE];
__device__ __nv_bfloat16 g_fwhi[VT*EE], g_fwlo[VT*EE];

// ---------------- fp32 -> bf16 hi/lo split (weights only) ----------------
__global__ void split_kernel(const float* __restrict__ in,
                             __nv_bfloat16* __restrict__ hi,
                             __nv_bfloat16* __restrict__ lo, int n4) {
    int i = blockIdx.x * blockDim.x + threadIdx.x;
    if (i >= n4) return;
    float4 v = ((const float4*)in)[i];
    __nv_bfloat16 h[4], l[4];
    float f[4] = { v.x, v.y, v.z, v.w };
#pragma unroll
    for (int j = 0; j < 4; j++) {
        h[j] = __float2bfloat16(f[j]);
        l[j] = __float2bfloat16(f[j] - __bfloat162float(h[j]));
    }
    ((uint2*)hi)[i] = *(uint2*)h;
    ((uint2*)lo)[i] = *(uint2*)l;
}

// ---------------- mma.sync / ldmatrix helpers ----------------
__device__ __forceinline__ void mma16816(float* d, const uint32_t* a, const uint32_t* b) {
    asm volatile(
        "mma.sync.aligned.m16n8k16.row.col.f32.bf16.bf16.f32 "
        "{%0,%1,%2,%3}, {%4,%5,%6,%7}, {%8,%9}, {%0,%1,%2,%3};"
        : "+f"(d[0]), "+f"(d[1]), "+f"(d[2]), "+f"(d[3])
        : "r"(a[0]), "r"(a[1]), "r"(a[2]), "r"(a[3]), "r"(b[0]), "r"(b[1]));
}
__device__ __forceinline__ void ldsm_x4(uint32_t* r, uint32_t addr) {
    asm volatile("ldmatrix.sync.aligned.m8n8.x4.shared.b16 {%0,%1,%2,%3}, [%4];"
        : "=r"(r[0]), "=r"(r[1]), "=r"(r[2]), "=r"(r[3]) : "r"(addr));
}
__device__ __forceinline__ uint32_t smem_u32(const void* p) {
    uint32_t a;
    asm("{ .reg .u64 t; cvta.to.shared.u64 t, %1; cvt.u32.u64 %0, t; }" : "=r"(a) : "l"(p));
    return a;
}
__device__ __forceinline__ void cp16(uint32_t dst, const void* src) {
    asm volatile("cp.async.cg.shared.global [%0], [%1], 16;" :: "r"(dst), "l"(src));
}

// ---------------- bf16 split GEMM: mma.sync + 2-stage cp.async + ldmatrix (R13) ----------------
#define SMW 36
#define TILE_WORDS (128 * SMW)
#define BUF_WORDS  (4 * TILE_WORDS)
#define GEMM_SMEM  (2 * BUF_WORDS * 4)
__global__ __launch_bounds__(256)
void gemm_mma(const __nv_bfloat16* __restrict__ Ahi, const __nv_bfloat16* __restrict__ Alo,
              const __nv_bfloat16* __restrict__ Bhi, const __nv_bfloat16* __restrict__ Blo,
              const float* __restrict__ bias, float* __restrict__ C, int N) {
    extern __shared__ uint32_t sm[];
    const uint32_t sbase = smem_u32(sm);

    const int tid  = threadIdx.x;
    const int lane = tid & 31;
    const int wid  = tid >> 5;
    const int n0 = blockIdx.x * 128, m0 = blockIdx.y * 128;
    const int m0w = (wid & 1) * 64;
    const int n0w = (wid >> 1) * 32;
    const int lr = lane >> 2;
    const int lc = lane & 3;

    const int ra = (lane & 7) + ((lane >> 3) & 1) * 8;
    const int wa = (lane >> 4) * 4;
    const int rb = (lane & 7) + (lane >> 4) * 8;
    const int wb = ((lane >> 3) & 1) * 4;

    const __nv_bfloat16* bases[4] = {
        Ahi + (size_t)m0 * 512, Alo + (size_t)m0 * 512,
        Bhi + (size_t)n0 * 512, Blo + (size_t)n0 * 512 };

    const int lrow[4] = { (tid + 0) >> 3, (tid + 256) >> 3, (tid + 512) >> 3, (tid + 768) >> 3 };
    const int lg = tid & 7;

    auto load_buf = [&](int buf, int kc) {
        const int k0 = kc * 64;
        const uint32_t d0 = sbase + (uint32_t)buf * BUF_WORDS * 4;
#pragma unroll
        for (int tl = 0; tl < 4; tl++) {
            const __nv_bfloat16* s = bases[tl] + k0;
            const uint32_t dt = d0 + (uint32_t)tl * TILE_WORDS * 4;
#pragma unroll
            for (int i = 0; i < 4; i++) {
                int row = lrow[i];
                cp16(dt + (uint32_t)(row * SMW + lg * 4) * 4,
                     s + (size_t)row * 512 + lg * 8);
            }
        }
        asm volatile("cp.async.commit_group;" ::: "memory");
    };

    float acc[4][4][4];
#pragma unroll
    for (int i = 0; i < 4; i++)
#pragma unroll
        for (int j = 0; j < 4; j++)
#pragma unroll
            for (int q = 0; q < 4; q++) acc[i][j][q] = 0.f;

    load_buf(0, 0);

    for (int kc = 0; kc < 8; kc++) {
        if (kc + 1 < 8) {
            load_buf((kc + 1) & 1, kc + 1);
            asm volatile("cp.async.wait_group 1;" ::: "memory");
        } else {
            asm volatile("cp.async.wait_group 0;" ::: "memory");
        }
        __syncthreads();

        const uint32_t uAhi = sbase + (uint32_t)(kc & 1) * BUF_WORDS * 4;
        const uint32_t uAlo = uAhi + TILE_WORDS * 4;
        const uint32_t uBhi = uAhi + 2 * TILE_WORDS * 4;
        const uint32_t uBlo = uAhi + 3 * TILE_WORDS * 4;

#pragma unroll
        for (int kk = 0; kk < 4; kk++) {
            uint32_t ah[4][4], al[4][4], bh[4][2], bl[4][2];
#pragma unroll
            for (int mt = 0; mt < 4; mt++) {
                uint32_t off = (uint32_t)((m0w + mt * 16 + ra) * SMW + kk * 8 + wa) * 4;
                ldsm_x4(ah[mt], uAhi + off);
                ldsm_x4(al[mt], uAlo + off);
            }
#pragma unroll
            for (int p = 0; p < 2; p++) {
                uint32_t off = (uint32_t)((n0w + p * 16 + rb) * SMW + kk * 8 + wb) * 4;
                uint32_t rh[4], rl[4];
                ldsm_x4(rh, uBhi + off);
                ldsm_x4(rl, uBlo + off);
                bh[p*2][0] = rh[0]; bh[p*2][1] = rh[1];
                bh[p*2+1][0] = rh[2]; bh[p*2+1][1] = rh[3];
                bl[p*2][0] = rl[0]; bl[p*2][1] = rl[1];
                bl[p*2+1][0] = rl[2]; bl[p*2+1][1] = rl[3];
            }
#pragma unroll
            for (int mt = 0; mt < 4; mt++)
#pragma unroll
                for (int nt = 0; nt < 4; nt++) {
                    mma16816(acc[mt][nt], ah[mt], bh[nt]);
                    mma16816(acc[mt][nt], ah[mt], bl[nt]);
                    mma16816(acc[mt][nt], al[mt], bh[nt]);
                }
        }
        __syncthreads();
    }

#pragma unroll
    for (int nt = 0; nt < 4; nt++) {
        int col = n0 + n0w + nt * 8 + lc * 2;
        float2 bv = *(const float2*)&bias[col];
#pragma unroll
        for (int mt = 0; mt < 4; mt++) {
            int r = m0 + m0w + mt * 16 + lr;
            *(float2*)&C[(size_t)r * N + col] =
                make_float2(acc[mt][nt][0] + bv.x, acc[mt][nt][1] + bv.y);
            *(float2*)&C[(size_t)(r + 8) * N + col] =
                make_float2(acc[mt][nt][2] + bv.x, acc[mt][nt][3] + bv.y);
        }
    }
}

// ---------------- embedding gather, writes hi/lo bf16 directly ----------------
__global__ void embed_kernel(const int* __restrict__ idx,
                             const float* __restrict__ emb,
                             __nv_bfloat16* __restrict__ hi,
                             __nv_bfloat16* __restrict__ lo) {
    int row = blockIdx.x;
    int v   = idx[row];
    float4 f = ((const float4*)(emb + (size_t)v * EE))[threadIdx.x];
    float fv[4] = { f.x, f.y, f.z, f.w };
    __nv_bfloat16 h[4], l[4];
#pragma unroll
    for (int j = 0; j < 4; j++) {
        h[j] = __float2bfloat16(fv[j]);
        l[j] = __float2bfloat16(fv[j] - __bfloat162float(h[j]));
    }
    ((uint2*)(hi + (size_t)row * EE))[threadIdx.x] = *(uint2*)h;
    ((uint2*)(lo + (size_t)row * EE))[threadIdx.x] = *(uint2*)l;
}

// ---------------- packed f32x2 helpers ----------------
__device__ __forceinline__ void fma2(unsigned long long &acc,
                                     unsigned long long a, unsigned long long b) {
    asm("fma.rn.f32x2 %0, %1, %2, %0;" : "+l"(acc) : "l"(a), "l"(b));
}
__device__ __forceinline__ float lo32(unsigned long long v) { return __uint_as_float((unsigned)v); }
__device__ __forceinline__ float hi32(unsigned long long v) { return __uint_as_float((unsigned)(v >> 32)); }

__device__ __forceinline__ float sigmoidf_(float x) { return 1.0f / (1.0f + expf(-x)); }

// ---------------- persistent LSTM layer: 4 groups x 32 blocks x 256 threads ----------------
// Group grp handles batches [grp*4, grp*4+4). Block lbk (0..31) owns k-slice
// [lbk*16, lbk*16+16) -> 64 Whh rows (4 gates x 16 k). Thread (jj = tid&63 row,
// seg = tid>>6 of 4 k-segments x 128) holds 128 weight floats in registers.
// Barrier: single-hop all-poll over the group's 32 padded flags (1 load/lane),
// warp 0 polls AFTER pointwise (R13 placement).
__global__ __launch_bounds__(256)
void lstm_layer(const float* __restrict__ xW, const float* __restrict__ Whh,
                __nv_bfloat16* __restrict__ xhi, __nv_bfloat16* __restrict__ xlo,
                const float* __restrict__ h0, const float* __restrict__ c0,
                float* __restrict__ hN, float* __restrict__ cN) {
    __shared__ float h_s[4 * HH];           // 8KB: 4 local batches x 512
    __shared__ float red[4 * 4 * 65];       // [b][seg][row pad65]
    __shared__ float c_s[16][4];            // [kx][b]
    __shared__ unsigned s_base;

    const int tid = threadIdx.x;
    const int bk  = blockIdx.x;             // 0..127
    const int grp = bk >> 5;                // batch group 0..3
    const int lbk = bk & 31;
    const int k0  = lbk * 16;
    const int jj  = tid & 63;               // row 0..63
    const int seg = tid >> 6;               // k-segment 0..3 (x128 k)
    const int gate = jj >> 4;
    const int jrow = gate * 512 + k0 + (jj & 15);
    const int b0flag = grp * 32;

    if (tid == 0) s_base = *(volatile unsigned*)&g_flags[bk * 32];

    // Whh slice -> registers: 128 floats = 64 f32x2 pairs
    unsigned long long w2[64];
    {
        const float* wr = Whh + (size_t)jrow * 512 + seg * 128;
#pragma unroll
        for (int u = 0; u < 64; u++)
            w2[u] = *reinterpret_cast<const unsigned long long*>(wr + u * 2);
    }

    // pointwise mapping (tid < 64): pb = batch 0..3, pkx = k 0..15
    const int pb = tid & 3, pkx = tid >> 2;
    const size_t xw_pbase = ((size_t)(grp * 4 + pb) * TT) * G4 + k0 + pkx;

    float h_last = 0.f, c_last = 0.f;
    if (tid < 64) {
        int gbat = grp * 4 + pb, k = k0 + pkx;
        c_s[pkx][pb] = c0 ? c0[gbat * HH + k] : 0.f;
        g_hbuf[0][gbat * HH + k] = h0 ? h0[gbat * HH + k] : 0.f;
    }
    __syncthreads();
    unsigned base = s_base;
    unsigned target = base + 1;

    // initial publish of h/c
    if (tid == 0) {
        __threadfence();
        *(volatile unsigned*)&g_flags[bk * 32] = target;
    }
    if (tid < 32) {
        for (;;) {
            unsigned v = *(volatile unsigned*)&g_flags[(b0flag + tid) * 32];
            if (__all_sync(0xffffffffu, (int)(v - target) >= 0)) break;
        }
    }
    __syncthreads();

    for (int t = 0; t < TT; t++) {
        // prefetch this step's 4 gate xW values (pointwise threads only)
        float xg[4];
        if (tid < 64) {
            const float* xp = xW + xw_pbase + (size_t)t * G4;
#pragma unroll
            for (int g = 0; g < 4; g++) xg[g] = __ldg(xp + g * 512);
        }

        // load group's h slice (4 batches x 512 = 2K floats = 512 float4)
        {
            const float4* gh4 = (const float4*)g_hbuf[t & 1] + grp * 512;
            float4* hs4 = (float4*)h_s;
#pragma unroll
            for (int u = 0; u < 2; u++)
                hs4[tid + u * 256] = __ldcg(gh4 + tid + u * 256);
        }
        __syncthreads();

        // partial dot: acc[b] over this thread's 128 k
        unsigned long long acc[4];
#pragma unroll
        for (int b = 0; b < 4; b++) acc[b] = 0ull;
#pragma unroll
        for (int u = 0; u < 64; u += 2) {
            const unsigned long long wa = w2[u], wb = w2[u + 1];
#pragma unroll
            for (int b = 0; b < 4; b++) {
                ulonglong2 hv = *reinterpret_cast<const ulonglong2*>(
                    &h_s[b * HH + seg * 128 + u * 2]);
                fma2(acc[b], wa, hv.x);
                fma2(acc[b], wb, hv.y);
            }
        }
#pragma unroll
        for (int b = 0; b < 4; b++)
            red[(b * 4 + seg) * 65 + jj] = lo32(acc[b]) + hi32(acc[b]);
        __syncthreads();

        // fused gather + pointwise (warps 0-1)
        if (tid < 64) {
            float gv[4];
#pragma unroll
            for (int g = 0; g < 4; g++) {
                float p = xg[g];
#pragma unroll
                for (int s = 0; s < 4; s++)
                    p += red[(pb * 4 + s) * 65 + g * 16 + pkx];
                gv[g] = p;
            }
            int gbat = grp * 4 + pb, k = k0 + pkx;
            float cold = c_s[pkx][pb];
            float cn = sigmoidf_(gv[1]) * cold + sigmoidf_(gv[0]) * tanhf(gv[2]);
            float hn = sigmoidf_(gv[3]) * tanhf(cn);
            c_s[pkx][pb] = cn;
            h_last = hn; c_last = cn;
            g_hbuf[(t + 1) & 1][gbat * HH + k] = hn;
            __nv_bfloat16 hh = __float2bfloat16(hn);
            __nv_bfloat16 hl = __float2bfloat16(hn - __bfloat162float(hh));
            size_t xo = ((size_t)gbat * TT + t) * HH + k;
            xhi[xo] = hh;
            xlo[xo] = hl;
            asm volatile("bar.sync 1, 64;" ::: "memory");
            if (tid == 0) {
                __threadfence();
                *(volatile unsigned*)&g_flags[bk * 32] = target + 1;
            }
        }
        ++target;
        // warp 0 polls the group's 32 flags after pointwise
        if (tid < 32) {
            for (;;) {
                unsigned v = *(volatile unsigned*)&g_flags[(b0flag + tid) * 32];
                if (__all_sync(0xffffffffu, (int)(v - target) >= 0)) break;
            }
        }
        __syncthreads();
    }

    if (hN != nullptr && tid < 64) {
        int gbat = grp * 4 + pb, k = k0 + pkx;
        hN[gbat * HH + k] = h_last;
        cN[gbat * HH + k] = c_last;
    }
}

// ---------------- host orchestration ----------------
extern "C" void kernel_launch(void* const* d_in, const int* in_sizes, int n_in,
                              void* d_out, int out_size) {
    (void)in_sizes; (void)n_in; (void)out_size;
    const int*   src     = (const int*)  d_in[0];
    const int*   tgt     = (const int*)  d_in[1];
    const float* src_emb = (const float*)d_in[2];
    const float* tgt_emb = (const float*)d_in[3];
    const float* enc_Wih = (const float*)d_in[4];
    const float* enc_Whh = (const float*)d_in[5];
    const float* enc_b   = (const float*)d_in[6];
    const float* dec_Wih = (const float*)d_in[7];
    const float* dec_Whh = (const float*)d_in[8];
    const float* dec_b   = (const float*)d_in[9];
    const float* fc_W    = (const float*)d_in[10];
    const float* fc_b    = (const float*)d_in[11];
    float* out = (float*)d_out;

    float *xw, *hN, *cN;
    __nv_bfloat16 *ahi, *alo, *bhi, *blo, *whi, *wlo, *fwhi, *fwlo;
    cudaGetSymbolAddress((void**)&xw, g_xW);
    cudaGetSymbolAddress((void**)&hN, g_hN);
    cudaGetSymbolAddress((void**)&cN, g_cN);
    cudaGetSymbolAddress((void**)&ahi, g_ahi);
    cudaGetSymbolAddress((void**)&alo, g_alo);
    cudaGetSymbolAddress((void**)&bhi, g_bhi);
    cudaGetSymbolAddress((void**)&blo, g_blo);
    cudaGetSymbolAddress((void**)&whi, g_whi);
    cudaGetSymbolAddress((void**)&wlo, g_wlo);
    cudaGetSymbolAddress((void**)&fwhi, g_fwhi);
    cudaGetSymbolAddress((void**)&fwlo, g_fwlo);

    cudaFuncSetAttribute(gemm_mma, cudaFuncAttributeMaxDynamicSharedMemorySize, GEMM_SMEM);

    const int WN4 = G4 * EE / 4;
    const int FN4 = VT * EE / 4;

    split_kernel<<<(FN4 + 255) / 256, 256>>>(fc_W, fwhi, fwlo, FN4);

    __nv_bfloat16* phi[2] = { ahi, bhi };
    __nv_bfloat16* plo[2] = { alo, blo };

    // ---- encoder ----
    embed_kernel<<<NTOK, 128>>>(src, src_emb, ahi, alo);
    for (int l = 0; l < NLY; l++) {
        int ri = l & 1, wi = ri ^ 1;
        split_kernel<<<(WN4 + 255) / 256, 256>>>(enc_Wih + (size_t)l * G4 * EE, whi, wlo, WN4);
        gemm_mma<<<dim3(G4 / 128, NTOK / 128), 256, GEMM_SMEM>>>(
            phi[ri], plo[ri], whi, wlo, enc_b + l * G4, xw, G4);
        lstm_layer<<<NBLK, 256>>>(xw, enc_Whh + (size_t)l * G4 * HH,
                                  phi[wi], plo[wi], nullptr, nullptr,
                                  hN + l * BB * HH, cN + l * BB * HH);
    }
    // ---- decoder ----
    embed_kernel<<<NTOK, 128>>>(tgt, tgt_emb, ahi, alo);
    for (int l = 0; l < NLY; l++) {
        int ri = l & 1, wi = ri ^ 1;
        split_kernel<<<(WN4 + 255) / 256, 256>>>(dec_Wih + (size_t)l * G4 * EE, whi, wlo, WN4);
        gemm_mma<<<dim3(G4 / 128, NTOK / 128), 256, GEMM_SMEM>>>(
            phi[ri], plo[ri], whi, wlo, dec_b + l * G4, xw, G4);
        lstm_layer<<<NBLK, 256>>>(xw, dec_Whh + (size_t)l * G4 * HH,
                                  phi[wi], plo[wi],
                                  hN + l * BB * HH, cN + l * BB * HH,
                                  nullptr, nullptr);
    }
    // ---- vocab projection (decoder l=3 wrote pair A) ----
    gemm_mma<<<dim3(VT / 128, NTOK / 128), 256, GEMM_SMEM>>>(
        ahi, alo, fwhi, fwlo, fc_b, out, VT);
}